// round 1
// baseline (speedup 1.0000x reference)
#include <cuda_runtime.h>
#include <cuda_bf16.h>
#include <math.h>

// Problem constants
#define BB 4
#define SS 4096
#define DD 2048
#define HHH 16
#define DHH 128
#define MTOT (BB*SS)          // 16384 tokens

// GEMM tiling
#define BM 128
#define BN 128
#define BKT 32
#define LDK 36                // BK + 4 pad  -> A fragment loads conflict-free
#define LDN 136               // BN + 8 pad  -> B fragment loads conflict-free
#define ASZ (BM*LDK)          // 4608 floats
#define BSZ (BKT*LDN)         // 4352 floats
#define SMEM_BYTES (2*(ASZ+BSZ)*4)   // 71680 B (double buffered)

#define MDIM 16384
#define NDIM 2048
#define KDIM 2048

// ---------------- scratch (no allocation allowed) ----------------
__device__ float g_Q [(size_t)MTOT*DD];
__device__ float g_K [(size_t)MTOT*DD];
__device__ float g_V [(size_t)MTOT*DD];
__device__ float g_X1[(size_t)MTOT*DD];
__device__ float g_Hb[(size_t)MTOT*DD];
__device__ float g_Y2[(size_t)MTOT*DD];

// ---------------- small helpers ----------------
__device__ __forceinline__ unsigned f2tf(float f) {
    unsigned u;
    asm("cvt.rna.tf32.f32 %0, %1;" : "=r"(u) : "f"(f));
    return u;
}

__device__ __forceinline__ void mma_tf32(float* d, const unsigned* a, const unsigned* b, const float* c) {
    asm volatile(
        "mma.sync.aligned.m16n8k8.row.col.f32.tf32.tf32.f32 "
        "{%0,%1,%2,%3}, {%4,%5,%6,%7}, {%8,%9}, {%10,%11,%12,%13};\n"
        : "=f"(d[0]), "=f"(d[1]), "=f"(d[2]), "=f"(d[3])
        : "r"(a[0]), "r"(a[1]), "r"(a[2]), "r"(a[3]),
          "r"(b[0]), "r"(b[1]),
          "f"(c[0]), "f"(c[1]), "f"(c[2]), "f"(c[3]));
}

__device__ __forceinline__ void cp_async16(void* smem, const void* gmem) {
    unsigned s = (unsigned)__cvta_generic_to_shared(smem);
    asm volatile("cp.async.cg.shared.global [%0], [%1], 16;\n" :: "r"(s), "l"(gmem));
}
#define CP_COMMIT() asm volatile("cp.async.commit_group;\n" ::: "memory")
#define CP_WAIT0()  asm volatile("cp.async.wait_group 0;\n" ::: "memory")

__device__ __forceinline__ float gelu_exact(float x) {
    return 0.5f * x * (1.0f + erff(x * 0.7071067811865476f));
}

// ---------------- TF32 tensor-core GEMM: C[M,N] = A[M,K] @ W[K,N] + bias (opt GELU) ----------------
template<bool GELU>
__global__ __launch_bounds__(256) void gemm_tf32(const float* __restrict__ A,
                                                 const float* __restrict__ W,
                                                 const float* __restrict__ bias,
                                                 float* __restrict__ C) {
    extern __shared__ float sm[];
    float* As0 = sm;
    float* As1 = sm + ASZ;
    float* Bs0 = sm + 2*ASZ;
    float* Bs1 = sm + 2*ASZ + BSZ;
    float* Asm[2] = { As0, As1 };
    float* Bsm[2] = { Bs0, Bs1 };

    const int tid = threadIdx.x;
    const int bn = blockIdx.x, bm = blockIdx.y;

    const float* Ablk = A + (size_t)bm * BM * KDIM;
    const float* Wblk = W + bn * BN;

    // global->smem load assignments
    const int aRow = tid >> 3;            // 0..31 (+32 per pass)
    const int aCol = (tid & 7) * 4;       // 0..28
    const int bRow = tid >> 5;            // 0..7  (+8 per pass)
    const int bCol = (tid & 31) * 4;      // 0..124

    const int warp = tid >> 5, lane = tid & 31;
    const int wm = warp & 3, wn = warp >> 2;   // warp tile: 32 rows x 64 cols
    const int g  = lane >> 2, tg = lane & 3;
    const int mrow = wm * 32;
    const int ncol = wn * 64;

    float acc[2][8][4];
    #pragma unroll
    for (int mi = 0; mi < 2; mi++)
        #pragma unroll
        for (int ni = 0; ni < 8; ni++)
            #pragma unroll
            for (int r = 0; r < 4; r++) acc[mi][ni][r] = 0.f;

    // stage loader
    auto load_stage = [&](int st, int kt) {
        const int k0 = kt * BKT;
        #pragma unroll
        for (int p = 0; p < 4; p++) {
            int r = aRow + p * 32;
            cp_async16(&Asm[st][r * LDK + aCol], Ablk + (size_t)r * KDIM + k0 + aCol);
        }
        #pragma unroll
        for (int p = 0; p < 4; p++) {
            int r = bRow + p * 8;
            cp_async16(&Bsm[st][r * LDN + bCol], Wblk + (size_t)(k0 + r) * NDIM + bCol);
        }
        CP_COMMIT();
    };

    load_stage(0, 0);
    const int KT = KDIM / BKT;   // 64
    for (int kt = 0; kt < KT; kt++) {
        CP_WAIT0();
        __syncthreads();
        const int st = kt & 1;
        if (kt + 1 < KT) load_stage(st ^ 1, kt + 1);

        const float* ap = Asm[st];
        const float* bp = Bsm[st];
        #pragma unroll
        for (int kk = 0; kk < 4; kk++) {
            const int ks = kk * 8;
            unsigned afr[2][4];
            #pragma unroll
            for (int mi = 0; mi < 2; mi++) {
                const int r0 = mrow + mi * 16;
                afr[mi][0] = f2tf(ap[(r0 + g    ) * LDK + ks + tg    ]);
                afr[mi][1] = f2tf(ap[(r0 + g + 8) * LDK + ks + tg    ]);
                afr[mi][2] = f2tf(ap[(r0 + g    ) * LDK + ks + tg + 4]);
                afr[mi][3] = f2tf(ap[(r0 + g + 8) * LDK + ks + tg + 4]);
            }
            unsigned bfr[8][2];
            #pragma unroll
            for (int ni = 0; ni < 8; ni++) {
                const int c0 = ncol + ni * 8 + g;
                bfr[ni][0] = f2tf(bp[(ks + tg    ) * LDN + c0]);
                bfr[ni][1] = f2tf(bp[(ks + tg + 4) * LDN + c0]);
            }
            #pragma unroll
            for (int mi = 0; mi < 2; mi++)
                #pragma unroll
                for (int ni = 0; ni < 8; ni++)
                    mma_tf32(acc[mi][ni], afr[mi], bfr[ni], acc[mi][ni]);
        }
    }

    // epilogue
    #pragma unroll
    for (int mi = 0; mi < 2; mi++) {
        #pragma unroll
        for (int ni = 0; ni < 8; ni++) {
            const int row0 = bm * BM + mrow + mi * 16 + g;
            const int col0 = bn * BN + ncol + ni * 8 + tg * 2;
            const float b0 = bias[col0], b1v = bias[col0 + 1];
            float v0 = acc[mi][ni][0] + b0;
            float v1 = acc[mi][ni][1] + b1v;
            float v2 = acc[mi][ni][2] + b0;
            float v3 = acc[mi][ni][3] + b1v;
            if (GELU) { v0 = gelu_exact(v0); v1 = gelu_exact(v1); v2 = gelu_exact(v2); v3 = gelu_exact(v3); }
            float2 lo = make_float2(v0, v1);
            float2 hi = make_float2(v2, v3);
            *reinterpret_cast<float2*>(&C[(size_t)row0 * NDIM + col0])       = lo;
            *reinterpret_cast<float2*>(&C[(size_t)(row0 + 8) * NDIM + col0]) = hi;
        }
    }
}

// ---------------- fused per-token attention + residual + LN1 ----------------
// attention is over HEADS within one token: q,k,v are [16,128]; scores 16x16.
__global__ __launch_bounds__(256) void attn_ln1_kernel(const float* __restrict__ X,
                                                       const float* __restrict__ g1,
                                                       const float* __restrict__ be1,
                                                       float* __restrict__ X1) {
    __shared__ float qs[16 * 128];
    __shared__ float ks2[16 * 129];   // pad 129 -> conflict-free k reads
    __shared__ float vs[16 * 128];
    __shared__ float att[256];
    __shared__ float ybuf[2048];
    __shared__ float red[16];

    const int tok = blockIdx.x;
    const int tid = threadIdx.x;
    const size_t base = (size_t)tok * 2048;

    for (int i = tid; i < 2048; i += 256) {
        const int h = i >> 7, d = i & 127;
        qs[i] = g_Q[base + i];
        ks2[h * 129 + d] = g_K[base + i];
        vs[i] = g_V[base + i];
    }
    __syncthreads();

    // scores: thread (h,t)
    {
        const int h = tid >> 4, t = tid & 15;
        float s = 0.f;
        #pragma unroll 8
        for (int d = 0; d < 128; d++) s += qs[h * 128 + d] * ks2[t * 129 + d];
        s *= 0.08838834764831845f;   // 1/sqrt(128)
        float mx = s;
        #pragma unroll
        for (int o = 8; o > 0; o >>= 1) mx = fmaxf(mx, __shfl_xor_sync(0xffffffffu, mx, o, 16));
        const float e = __expf(s - mx);
        float sum = e;
        #pragma unroll
        for (int o = 8; o > 0; o >>= 1) sum += __shfl_xor_sync(0xffffffffu, sum, o, 16);
        att[h * 16 + t] = e / sum;
    }
    __syncthreads();

    // y = att @ v
    {
        const int h2 = tid >> 4, dg = tid & 15;
        #pragma unroll
        for (int j = 0; j < 8; j++) {
            const int d = dg + j * 16;
            float y = 0.f;
            #pragma unroll
            for (int tt = 0; tt < 16; tt++) y += att[h2 * 16 + tt] * vs[tt * 128 + d];
            ybuf[h2 * 128 + d] = y;
        }
    }
    __syncthreads();

    // residual + LayerNorm
    float z[8];
    float s1 = 0.f, s2 = 0.f;
    #pragma unroll
    for (int j = 0; j < 8; j++) {
        const int i = tid + j * 256;
        z[j] = X[base + i] + ybuf[i];
        s1 += z[j];
        s2 += z[j] * z[j];
    }
    #pragma unroll
    for (int o = 16; o > 0; o >>= 1) {
        s1 += __shfl_xor_sync(0xffffffffu, s1, o);
        s2 += __shfl_xor_sync(0xffffffffu, s2, o);
    }
    if ((tid & 31) == 0) { red[(tid >> 5) * 2] = s1; red[(tid >> 5) * 2 + 1] = s2; }
    __syncthreads();
    float t1 = 0.f, t2 = 0.f;
    #pragma unroll
    for (int w = 0; w < 8; w++) { t1 += red[w * 2]; t2 += red[w * 2 + 1]; }
    const float mean = t1 * (1.f / 2048.f);
    const float var  = t2 * (1.f / 2048.f) - mean * mean;
    const float inv  = rsqrtf(var + 1e-5f);
    #pragma unroll
    for (int j = 0; j < 8; j++) {
        const int i = tid + j * 256;
        X1[base + i] = (z[j] - mean) * inv * g1[i] + be1[i];
    }
}

// ---------------- add + LayerNorm (final) ----------------
__global__ __launch_bounds__(256) void add_ln_kernel(const float* __restrict__ A,
                                                     const float* __restrict__ Bv,
                                                     const float* __restrict__ g,
                                                     const float* __restrict__ be,
                                                     float* __restrict__ out) {
    __shared__ float red[16];
    const int row = blockIdx.x;
    const int tid = threadIdx.x;
    const size_t base = (size_t)row * 2048;

    float z[8];
    float s1 = 0.f, s2 = 0.f;
    #pragma unroll
    for (int j = 0; j < 8; j++) {
        const int i = tid + j * 256;
        z[j] = A[base + i] + Bv[base + i];
        s1 += z[j];
        s2 += z[j] * z[j];
    }
    #pragma unroll
    for (int o = 16; o > 0; o >>= 1) {
        s1 += __shfl_xor_sync(0xffffffffu, s1, o);
        s2 += __shfl_xor_sync(0xffffffffu, s2, o);
    }
    if ((tid & 31) == 0) { red[(tid >> 5) * 2] = s1; red[(tid >> 5) * 2 + 1] = s2; }
    __syncthreads();
    float t1 = 0.f, t2 = 0.f;
    #pragma unroll
    for (int w = 0; w < 8; w++) { t1 += red[w * 2]; t2 += red[w * 2 + 1]; }
    const float mean = t1 * (1.f / 2048.f);
    const float var  = t2 * (1.f / 2048.f) - mean * mean;
    const float inv  = rsqrtf(var + 1e-5f);
    #pragma unroll
    for (int j = 0; j < 8; j++) {
        const int i = tid + j * 256;
        out[base + i] = (z[j] - mean) * inv * g[i] + be[i];
    }
}

// ---------------- launch ----------------
extern "C" void kernel_launch(void* const* d_in, const int* in_sizes, int n_in,
                              void* d_out, int out_size) {
    const float* X    = (const float*)d_in[0];
    const float* Wq   = (const float*)d_in[1];
    const float* bq   = (const float*)d_in[2];
    const float* Wk   = (const float*)d_in[3];
    const float* bk   = (const float*)d_in[4];
    const float* Wv   = (const float*)d_in[5];
    const float* bv   = (const float*)d_in[6];
    const float* g1   = (const float*)d_in[7];
    const float* be1  = (const float*)d_in[8];
    const float* W1   = (const float*)d_in[9];
    const float* b1   = (const float*)d_in[10];
    const float* W2   = (const float*)d_in[11];
    const float* b2   = (const float*)d_in[12];
    const float* g2   = (const float*)d_in[13];
    const float* be2  = (const float*)d_in[14];
    float* out = (float*)d_out;

    float *Q, *K, *V, *X1, *Hb, *Y2;
    cudaGetSymbolAddress((void**)&Q,  g_Q);
    cudaGetSymbolAddress((void**)&K,  g_K);
    cudaGetSymbolAddress((void**)&V,  g_V);
    cudaGetSymbolAddress((void**)&X1, g_X1);
    cudaGetSymbolAddress((void**)&Hb, g_Hb);
    cudaGetSymbolAddress((void**)&Y2, g_Y2);

    cudaFuncSetAttribute(gemm_tf32<false>, cudaFuncAttributeMaxDynamicSharedMemorySize, SMEM_BYTES);
    cudaFuncSetAttribute(gemm_tf32<true>,  cudaFuncAttributeMaxDynamicSharedMemorySize, SMEM_BYTES);

    dim3 gblk(256);
    dim3 ggrd(NDIM / BN, MDIM / BM);   // (16, 128)

    gemm_tf32<false><<<ggrd, gblk, SMEM_BYTES>>>(X, Wq, bq, Q);
    gemm_tf32<false><<<ggrd, gblk, SMEM_BYTES>>>(X, Wk, bk, K);
    gemm_tf32<false><<<ggrd, gblk, SMEM_BYTES>>>(X, Wv, bv, V);

    attn_ln1_kernel<<<MTOT, 256>>>(X, g1, be1, X1);

    gemm_tf32<true> <<<ggrd, gblk, SMEM_BYTES>>>(X1, W1, b1, Hb);
    gemm_tf32<false><<<ggrd, gblk, SMEM_BYTES>>>(Hb, W2, b2, Y2);

    add_ln_kernel<<<MTOT, 256>>>(X1, Y2, g2, be2, out);
}

// round 9
// speedup vs baseline: 2.1079x; 2.1079x over previous
#include <cuda_runtime.h>
#include <cuda_bf16.h>
#include <math.h>
#include <stdint.h>

// ---------------- problem constants ----------------
#define MTOT 16384      // B*S tokens
#define DDIM 2048
#define KD   2048
#define ND   2048

// ---------------- GEMM tiling ----------------
#define BM 128
#define BN 256
#define SKF 32                  // K per stage
#define NSTG 3
#define LDK 36                  // padded A row (floats)
#define ASTG_F (BM*LDK)         // 4608 floats
#define BSTG_F ((BN/16)*4*32*4) // 16 pairs x 4 kblk x 32 lanes x 4 = 8192 floats
#define STG_F  (ASTG_F+BSTG_F)  // 12800 floats
#define GEMM_SMEM (NSTG*STG_F*4)  // 153600 B
#define KT_STEPS (KD/SKF)       // 64

// ---------------- scratch (no allocation allowed) ----------------
__device__ float g_Q  [(size_t)MTOT*DDIM];
__device__ float g_K  [(size_t)MTOT*DDIM];
__device__ float g_V  [(size_t)MTOT*DDIM];
__device__ float g_X1 [(size_t)MTOT*DDIM];
__device__ float g_X1r[(size_t)MTOT*DDIM];
__device__ float g_Hb [(size_t)MTOT*DDIM];
__device__ float g_Y2 [(size_t)MTOT*DDIM];
__device__ float g_Xr [(size_t)MTOT*DDIM];
__device__ float g_Wp [(size_t)5*KD*ND];   // frag-major permuted+rounded weights

// ---------------- helpers ----------------
__device__ __forceinline__ unsigned f2tf(float f) {
    unsigned u; asm("cvt.rna.tf32.f32 %0, %1;" : "=r"(u) : "f"(f)); return u;
}
__device__ __forceinline__ float rna(float f) { return __uint_as_float(f2tf(f)); }

__device__ __forceinline__ uint32_t smem_u32(const void* p) {
    uint32_t a;
    asm("{ .reg .u64 t; cvta.to.shared.u64 t, %1; cvt.u32.u64 %0, t; }" : "=r"(a) : "l"(p));
    return a;
}
__device__ __forceinline__ void cp_async16(uint32_t saddr, const void* g) {
    asm volatile("cp.async.cg.shared.global [%0], [%1], 16;" :: "r"(saddr), "l"(g) : "memory");
}
#define CP_COMMIT() asm volatile("cp.async.commit_group;" ::: "memory")
#define CP_WAIT1()  asm volatile("cp.async.wait_group 1;" ::: "memory")

__device__ __forceinline__ void mma_tf32(float* d, const unsigned* a, const unsigned* b) {
    asm volatile(
        "mma.sync.aligned.m16n8k8.row.col.f32.tf32.tf32.f32 "
        "{%0,%1,%2,%3}, {%4,%5,%6,%7}, {%8,%9}, {%0,%1,%2,%3};\n"
        : "+f"(d[0]), "+f"(d[1]), "+f"(d[2]), "+f"(d[3])
        : "r"(a[0]), "r"(a[1]), "r"(a[2]), "r"(a[3]),
          "r"(b[0]), "r"(b[1]));
}

__device__ __forceinline__ float gelu_exact(float x) {
    return 0.5f * x * (1.0f + erff(x * 0.7071067811865476f));
}

// ---------------- TF32 mma.sync GEMM: C[M,N] = A[M,K] @ W[K,N] + bias ----------------
// A: row-major, pre-rounded to tf32. Bp: frag-major permuted weights.
// Block 128x256, 8 warps, warp tile 64x64.
template<bool GELU, bool ROUND>
__global__ __launch_bounds__(256, 1) void gemm_mma(const float* __restrict__ A,
                                                   const float* __restrict__ Bp,
                                                   const float* __restrict__ bias,
                                                   float* __restrict__ C) {
    extern __shared__ float sm[];
    const uint32_t sb0 = smem_u32(sm);
    const int tid = threadIdx.x;
    const int wid = tid >> 5, lane = tid & 31;
    const int g = lane >> 2, tg = lane & 3;
    const int wm = wid >> 2, wn = wid & 3;

    const int n0 = blockIdx.x * BN;
    const int m0 = blockIdx.y * BM;

    const float* Arow = A + (size_t)m0 * KD;
    const float* Bbase = Bp + ((size_t)(n0 >> 4) * 256) * 128;   // pair stride 256 kblks * 128 floats

    float acc[4][8][4];
    #pragma unroll
    for (int mi = 0; mi < 4; mi++)
        #pragma unroll
        for (int ni = 0; ni < 8; ni++)
            #pragma unroll
            for (int r = 0; r < 4; r++) acc[mi][ni][r] = 0.f;

    auto load_stage = [&](int st, int kt) {
        const uint32_t sa = sb0 + st * (STG_F * 4);
        const uint32_t sbB = sa + ASTG_F * 4;
        const int k0 = kt * SKF;
        #pragma unroll
        for (int i = 0; i < 4; i++) {            // A: 1024 x 16B
            const int c = tid + i * 256;
            const int r = c >> 3, cc = c & 7;
            cp_async16(sa + (r * LDK + cc * 4) * 4, Arow + (size_t)r * KD + k0 + cc * 4);
        }
        const int qb = kt * 4;
        #pragma unroll
        for (int i = 0; i < 8; i++) {            // B: 2048 x 16B
            const int c = tid + i * 256;
            const int ll = c & 31, qq = (c >> 5) & 3, pp = c >> 7;
            cp_async16(sbB + (((pp * 4 + qq) * 32 + ll) * 4) * 4,
                       Bbase + ((size_t)pp * 256 + qb + qq) * 128 + ll * 4);
        }
        CP_COMMIT();
    };

    load_stage(0, 0);
    load_stage(1, 1);

    int st = 0;
    for (int kt = 0; kt < KT_STEPS; kt++) {
        CP_WAIT1();
        __syncthreads();
        if (kt + 2 < KT_STEPS) load_stage((st + 2) % NSTG, kt + 2);
        else CP_COMMIT();   // keep group count uniform for CP_WAIT1

        const float* sa = sm + st * STG_F;
        const float* sbB = sa + ASTG_F;
        #pragma unroll
        for (int ks = 0; ks < 4; ks++) {
            unsigned af[4][4];
            #pragma unroll
            for (int mi = 0; mi < 4; mi++) {
                const float* ap = sa + (wm * 64 + mi * 16) * LDK + ks * 8;
                af[mi][0] = __float_as_uint(ap[(g    ) * LDK + tg    ]);
                af[mi][1] = __float_as_uint(ap[(g + 8) * LDK + tg    ]);
                af[mi][2] = __float_as_uint(ap[(g    ) * LDK + tg + 4]);
                af[mi][3] = __float_as_uint(ap[(g + 8) * LDK + tg + 4]);
            }
            unsigned bf[4][4];
            #pragma unroll
            for (int pp = 0; pp < 4; pp++) {
                const float4 v = *reinterpret_cast<const float4*>(
                    sbB + (((wn * 4 + pp) * 4 + ks) * 32 + lane) * 4);
                bf[pp][0] = __float_as_uint(v.x); bf[pp][1] = __float_as_uint(v.y);
                bf[pp][2] = __float_as_uint(v.z); bf[pp][3] = __float_as_uint(v.w);
            }
            #pragma unroll
            for (int mi = 0; mi < 4; mi++)
                #pragma unroll
                for (int pp = 0; pp < 4; pp++) {
                    mma_tf32(acc[mi][2 * pp    ], af[mi], &bf[pp][0]);
                    mma_tf32(acc[mi][2 * pp + 1], af[mi], &bf[pp][2]);
                }
        }
        st = (st + 1) % NSTG;
    }

    // epilogue straight from registers
    #pragma unroll
    for (int mi = 0; mi < 4; mi++) {
        #pragma unroll
        for (int ni = 0; ni < 8; ni++) {
            const int r0 = m0 + wm * 64 + mi * 16 + g;
            const int c0 = n0 + wn * 64 + ni * 8 + tg * 2;
            const float b0 = bias[c0], b1v = bias[c0 + 1];
            float v0 = acc[mi][ni][0] + b0;
            float v1 = acc[mi][ni][1] + b1v;
            float v2 = acc[mi][ni][2] + b0;
            float v3 = acc[mi][ni][3] + b1v;
            if (GELU) { v0 = gelu_exact(v0); v1 = gelu_exact(v1); v2 = gelu_exact(v2); v3 = gelu_exact(v3); }
            if (ROUND) { v0 = rna(v0); v1 = rna(v1); v2 = rna(v2); v3 = rna(v3); }
            *reinterpret_cast<float2*>(&C[(size_t)r0 * ND + c0])       = make_float2(v0, v1);
            *reinterpret_cast<float2*>(&C[(size_t)(r0 + 8) * ND + c0]) = make_float2(v2, v3);
        }
    }
}

// ---------------- weight permute: W[K,N] -> frag-major Bp ----------------
// Bp layout: [pair p=n/16][kblk q=k/8][lane][4]:
//   slot0 = W[q*8+tg][p*16+g], slot1 = W[q*8+tg+4][p*16+g],
//   slot2 = W[q*8+tg][p*16+8+g], slot3 = W[q*8+tg+4][p*16+8+g]  (all rna-rounded)
__global__ __launch_bounds__(256) void permute_w(const float* __restrict__ W,
                                                 float* __restrict__ Bp) {
    __shared__ float smw[128][17];
    const int tid = threadIdx.x;
    const int p = blockIdx.x;          // 0..127
    const int kc = blockIdx.y;         // 0..15 (128 k each)
    const int k0 = kc * 128;
    for (int i = tid; i < 128 * 16; i += 256) {
        const int r = i >> 4, c = i & 15;
        smw[r][c] = W[(size_t)(k0 + r) * ND + p * 16 + c];
    }
    __syncthreads();
    for (int j = tid; j < 16 * 32; j += 256) {
        const int q = j >> 5, l = j & 31, gg = l >> 2, tt = l & 3;
        float4 v;
        v.x = rna(smw[q * 8 + tt    ][gg]);
        v.y = rna(smw[q * 8 + tt + 4][gg]);
        v.z = rna(smw[q * 8 + tt    ][8 + gg]);
        v.w = rna(smw[q * 8 + tt + 4][8 + gg]);
        reinterpret_cast<float4*>(Bp)[((size_t)p * 256 + kc * 16 + q) * 32 + l] = v;
    }
}

// ---------------- elementwise tf32 round ----------------
__global__ __launch_bounds__(256) void round_tf32_kernel(const float* __restrict__ in,
                                                         float* __restrict__ out) {
    const size_t i = ((size_t)blockIdx.x * 256 + threadIdx.x);
    float4 v = reinterpret_cast<const float4*>(in)[i];
    v.x = rna(v.x); v.y = rna(v.y); v.z = rna(v.z); v.w = rna(v.w);
    reinterpret_cast<float4*>(out)[i] = v;
}

// ---------------- fused per-token attention + residual + LN1 ----------------
__global__ __launch_bounds__(256) void attn_ln1_kernel(const float* __restrict__ X,
                                                       const float* __restrict__ g1,
                                                       const float* __restrict__ be1,
                                                       float* __restrict__ X1,
                                                       float* __restrict__ X1r) {
    __shared__ float4 qs4[16 * 32];
    __shared__ float4 ks4[16 * 33];
    __shared__ float4 vs4[16 * 32];
    __shared__ float att[256];
    __shared__ float4 ybuf4[512];
    __shared__ float red[16];

    const int tok = blockIdx.x;
    const int tid = threadIdx.x;
    const size_t base = (size_t)tok * 2048;
    const size_t base4 = base >> 2;

    const float4* Q4 = reinterpret_cast<const float4*>(g_Q);
    const float4* K4 = reinterpret_cast<const float4*>(g_K);
    const float4* V4 = reinterpret_cast<const float4*>(g_V);

    for (int i = tid; i < 512; i += 256) {
        const int h = i >> 5, dd = i & 31;
        qs4[i] = Q4[base4 + i];
        ks4[h * 33 + dd] = K4[base4 + i];
        vs4[i] = V4[base4 + i];
    }
    __syncthreads();

    // scores (h,t)
    {
        const int h = tid >> 4, t = tid & 15;
        float s = 0.f;
        #pragma unroll
        for (int dd = 0; dd < 32; dd++) {
            const float4 q = qs4[h * 32 + dd];
            const float4 k = ks4[t * 33 + dd];
            s += q.x * k.x + q.y * k.y + q.z * k.z + q.w * k.w;
        }
        s *= 0.08838834764831845f;
        float mx = s;
        #pragma unroll
        for (int o = 8; o > 0; o >>= 1) mx = fmaxf(mx, __shfl_xor_sync(0xffffffffu, mx, o, 16));
        const float e = __expf(s - mx);
        float sum = e;
        #pragma unroll
        for (int o = 8; o > 0; o >>= 1) sum += __shfl_xor_sync(0xffffffffu, sum, o, 16);
        att[(tid >> 4) * 16 + t] = e / sum;
    }
    __syncthreads();

    // y = att @ v   (att hoisted to regs, float4 on v)
    {
        const int h2 = tid >> 4, dg = tid & 15;
        float a[16];
        #pragma unroll
        for (int tt = 0; tt < 16; tt++) a[tt] = att[h2 * 16 + tt];
        float4 y0 = make_float4(0.f, 0.f, 0.f, 0.f);
        float4 y1 = make_float4(0.f, 0.f, 0.f, 0.f);
        #pragma unroll
        for (int tt = 0; tt < 16; tt++) {
            const float4 v0 = vs4[tt * 32 + dg];
            const float4 v1 = vs4[tt * 32 + 16 + dg];
            y0.x += a[tt] * v0.x; y0.y += a[tt] * v0.y; y0.z += a[tt] * v0.z; y0.w += a[tt] * v0.w;
            y1.x += a[tt] * v1.x; y1.y += a[tt] * v1.y; y1.z += a[tt] * v1.z; y1.w += a[tt] * v1.w;
        }
        ybuf4[h2 * 32 + dg] = y0;
        ybuf4[h2 * 32 + 16 + dg] = y1;
    }
    __syncthreads();

    // residual + LN1
    const float4* X4 = reinterpret_cast<const float4*>(X);
    float4 z[2];
    float s1 = 0.f, s2 = 0.f;
    #pragma unroll
    for (int j = 0; j < 2; j++) {
        const int i = tid + j * 256;
        const float4 xv = X4[base4 + i];
        const float4 yv = ybuf4[i];
        z[j].x = xv.x + yv.x; z[j].y = xv.y + yv.y; z[j].z = xv.z + yv.z; z[j].w = xv.w + yv.w;
        s1 += z[j].x + z[j].y + z[j].z + z[j].w;
        s2 += z[j].x * z[j].x + z[j].y * z[j].y + z[j].z * z[j].z + z[j].w * z[j].w;
    }
    #pragma unroll
    for (int o = 16; o > 0; o >>= 1) {
        s1 += __shfl_xor_sync(0xffffffffu, s1, o);
        s2 += __shfl_xor_sync(0xffffffffu, s2, o);
    }
    if ((tid & 31) == 0) { red[(tid >> 5) * 2] = s1; red[(tid >> 5) * 2 + 1] = s2; }
    __syncthreads();
    float t1 = 0.f, t2 = 0.f;
    #pragma unroll
    for (int w = 0; w < 8; w++) { t1 += red[w * 2]; t2 += red[w * 2 + 1]; }
    const float mean = t1 * (1.f / 2048.f);
    const float var  = t2 * (1.f / 2048.f) - mean * mean;
    const float inv  = rsqrtf(var + 1e-5f);

    const float4* G4 = reinterpret_cast<const float4*>(g1);
    const float4* B4 = reinterpret_cast<const float4*>(be1);
    float4* X1o  = reinterpret_cast<float4*>(X1);
    float4* X1ro = reinterpret_cast<float4*>(X1r);
    #pragma unroll
    for (int j = 0; j < 2; j++) {
        const int i = tid + j * 256;
        const float4 gv = G4[i], bv = B4[i];
        float4 o, orr;
        o.x = (z[j].x - mean) * inv * gv.x + bv.x;
        o.y = (z[j].y - mean) * inv * gv.y + bv.y;
        o.z = (z[j].z - mean) * inv * gv.z + bv.z;
        o.w = (z[j].w - mean) * inv * gv.w + bv.w;
        orr.x = rna(o.x); orr.y = rna(o.y); orr.z = rna(o.z); orr.w = rna(o.w);
        X1o[base4 + i] = o;
        X1ro[base4 + i] = orr;
    }
}

// ---------------- add + LayerNorm (final) ----------------
__global__ __launch_bounds__(256) void add_ln_kernel(const float* __restrict__ A,
                                                     const float* __restrict__ Bv,
                                                     const float* __restrict__ g,
                                                     const float* __restrict__ be,
                                                     float* __restrict__ out) {
    __shared__ float red[16];
    const int row = blockIdx.x;
    const int tid = threadIdx.x;
    const size_t base4 = ((size_t)row * 2048) >> 2;

    const float4* A4 = reinterpret_cast<const float4*>(A);
    const float4* B4 = reinterpret_cast<const float4*>(Bv);
    float4 z[2];
    float s1 = 0.f, s2 = 0.f;
    #pragma unroll
    for (int j = 0; j < 2; j++) {
        const int i = tid + j * 256;
        const float4 av = A4[base4 + i];
        const float4 bv = B4[base4 + i];
        z[j].x = av.x + bv.x; z[j].y = av.y + bv.y; z[j].z = av.z + bv.z; z[j].w = av.w + bv.w;
        s1 += z[j].x + z[j].y + z[j].z + z[j].w;
        s2 += z[j].x * z[j].x + z[j].y * z[j].y + z[j].z * z[j].z + z[j].w * z[j].w;
    }
    #pragma unroll
    for (int o = 16; o > 0; o >>= 1) {
        s1 += __shfl_xor_sync(0xffffffffu, s1, o);
        s2 += __shfl_xor_sync(0xffffffffu, s2, o);
    }
    if ((tid & 31) == 0) { red[(tid >> 5) * 2] = s1; red[(tid >> 5) * 2 + 1] = s2; }
    __syncthreads();
    float t1 = 0.f, t2 = 0.f;
    #pragma unroll
    for (int w = 0; w < 8; w++) { t1 += red[w * 2]; t2 += red[w * 2 + 1]; }
    const float mean = t1 * (1.f / 2048.f);
    const float var  = t2 * (1.f / 2048.f) - mean * mean;
    const float inv  = rsqrtf(var + 1e-5f);

    const float4* G4 = reinterpret_cast<const float4*>(g);
    const float4* Be4 = reinterpret_cast<const float4*>(be);
    float4* O4 = reinterpret_cast<float4*>(out);
    #pragma unroll
    for (int j = 0; j < 2; j++) {
        const int i = tid + j * 256;
        const float4 gv = G4[i], bv = Be4[i];
        float4 o;
        o.x = (z[j].x - mean) * inv * gv.x + bv.x;
        o.y = (z[j].y - mean) * inv * gv.y + bv.y;
        o.z = (z[j].z - mean) * inv * gv.z + bv.z;
        o.w = (z[j].w - mean) * inv * gv.w + bv.w;
        O4[base4 + i] = o;
    }
}

// ---------------- launch ----------------
extern "C" void kernel_launch(void* const* d_in, const int* in_sizes, int n_in,
                              void* d_out, int out_size) {
    const float* X   = (const float*)d_in[0];
    const float* Wq  = (const float*)d_in[1];
    const float* bq  = (const float*)d_in[2];
    const float* Wk  = (const float*)d_in[3];
    const float* bk  = (const float*)d_in[4];
    const float* Wv  = (const float*)d_in[5];
    const float* bv  = (const float*)d_in[6];
    const float* g1  = (const float*)d_in[7];
    const float* be1 = (const float*)d_in[8];
    const float* W1  = (const float*)d_in[9];
    const float* b1  = (const float*)d_in[10];
    const float* W2  = (const float*)d_in[11];
    const float* b2  = (const float*)d_in[12];
    const float* g2  = (const float*)d_in[13];
    const float* be2 = (const float*)d_in[14];
    float* out = (float*)d_out;

    float *Q, *K, *V, *X1, *X1r, *Hb, *Y2, *Xr, *Wp;
    cudaGetSymbolAddress((void**)&Q,   g_Q);
    cudaGetSymbolAddress((void**)&K,   g_K);
    cudaGetSymbolAddress((void**)&V,   g_V);
    cudaGetSymbolAddress((void**)&X1,  g_X1);
    cudaGetSymbolAddress((void**)&X1r, g_X1r);
    cudaGetSymbolAddress((void**)&Hb,  g_Hb);
    cudaGetSymbolAddress((void**)&Y2,  g_Y2);
    cudaGetSymbolAddress((void**)&Xr,  g_Xr);
    cudaGetSymbolAddress((void**)&Wp,  g_Wp);

    cudaFuncSetAttribute(gemm_mma<false,false>, cudaFuncAttributeMaxDynamicSharedMemorySize, GEMM_SMEM);
    cudaFuncSetAttribute(gemm_mma<true,true>,   cudaFuncAttributeMaxDynamicSharedMemorySize, GEMM_SMEM);

    const size_t WSZ = (size_t)KD * ND;

    // pre-round X; permute+round weights to fragment-major
    round_tf32_kernel<<<(MTOT * (size_t)DDIM) / (256 * 4), 256>>>(X, Xr);
    dim3 pg(ND / 16, KD / 128);   // (128, 16)
    permute_w<<<pg, 256>>>(Wq, Wp + 0 * WSZ);
    permute_w<<<pg, 256>>>(Wk, Wp + 1 * WSZ);
    permute_w<<<pg, 256>>>(Wv, Wp + 2 * WSZ);
    permute_w<<<pg, 256>>>(W1, Wp + 3 * WSZ);
    permute_w<<<pg, 256>>>(W2, Wp + 4 * WSZ);

    dim3 gg(ND / BN, MTOT / BM);  // (8, 128)
    gemm_mma<false,false><<<gg, 256, GEMM_SMEM>>>(Xr, Wp + 0 * WSZ, bq, Q);
    gemm_mma<false,false><<<gg, 256, GEMM_SMEM>>>(Xr, Wp + 1 * WSZ, bk, K);
    gemm_mma<false,false><<<gg, 256, GEMM_SMEM>>>(Xr, Wp + 2 * WSZ, bv, V);

    attn_ln1_kernel<<<MTOT, 256>>>(X, g1, be1, X1, X1r);

    gemm_mma<true,true>  <<<gg, 256, GEMM_SMEM>>>(X1r, Wp + 3 * WSZ, b1, Hb);
    gemm_mma<false,false><<<gg, 256, GEMM_SMEM>>>(Hb,  Wp + 4 * WSZ, b2, Y2);

    add_ln_kernel<<<MTOT, 256>>>(X1, Y2, g2, be2, out);
}

// round 10
// speedup vs baseline: 2.1161x; 1.0039x over previous
#include <cuda_runtime.h>
#include <cuda_bf16.h>
#include <math.h>
#include <stdint.h>

// ---------------- problem constants ----------------
#define MTOT 16384      // B*S tokens
#define DDIM 2048
#define KD   2048
#define ND   2048

// ---------------- GEMM tiling ----------------
#define BM 128
#define BN 256
#define SKF 32                  // K per stage
#define NSTG 4
#define LDK 36                  // padded A row (floats)
#define ASTG_F (BM*LDK)         // 4608 floats
#define BSTG_F ((BN/16)*4*32*4) // 16 pairs x 4 kblk x 32 lanes x 4 = 8192 floats
#define STG_F  (ASTG_F+BSTG_F)  // 12800 floats
#define GEMM_SMEM (NSTG*STG_F*4)  // 204800 B
#define KT_STEPS (KD/SKF)       // 64

// ---------------- scratch (no allocation allowed) ----------------
__device__ float g_Q  [(size_t)MTOT*DDIM];
__device__ float g_K  [(size_t)MTOT*DDIM];
__device__ float g_V  [(size_t)MTOT*DDIM];
__device__ float g_X1 [(size_t)MTOT*DDIM];
__device__ float g_X1r[(size_t)MTOT*DDIM];
__device__ float g_Hb [(size_t)MTOT*DDIM];
__device__ float g_Y2 [(size_t)MTOT*DDIM];
__device__ float g_Xr [(size_t)MTOT*DDIM];
__device__ float g_Wp [(size_t)5*KD*ND];   // frag-major permuted+rounded weights

// ---------------- helpers ----------------
__device__ __forceinline__ unsigned f2tf(float f) {
    unsigned u; asm("cvt.rna.tf32.f32 %0, %1;" : "=r"(u) : "f"(f)); return u;
}
__device__ __forceinline__ float rna(float f) { return __uint_as_float(f2tf(f)); }

__device__ __forceinline__ uint32_t smem_u32(const void* p) {
    uint32_t a;
    asm("{ .reg .u64 t; cvta.to.shared.u64 t, %1; cvt.u32.u64 %0, t; }" : "=r"(a) : "l"(p));
    return a;
}
__device__ __forceinline__ void cp_async16(uint32_t saddr, const void* g) {
    asm volatile("cp.async.cg.shared.global [%0], [%1], 16;" :: "r"(saddr), "l"(g) : "memory");
}
#define CP_COMMIT() asm volatile("cp.async.commit_group;" ::: "memory")
#define CP_WAIT2()  asm volatile("cp.async.wait_group 2;" ::: "memory")

__device__ __forceinline__ void mma_tf32(float* d, const unsigned* a, const unsigned* b) {
    asm volatile(
        "mma.sync.aligned.m16n8k8.row.col.f32.tf32.tf32.f32 "
        "{%0,%1,%2,%3}, {%4,%5,%6,%7}, {%8,%9}, {%0,%1,%2,%3};\n"
        : "+f"(d[0]), "+f"(d[1]), "+f"(d[2]), "+f"(d[3])
        : "r"(a[0]), "r"(a[1]), "r"(a[2]), "r"(a[3]),
          "r"(b[0]), "r"(b[1]));
}

__device__ __forceinline__ float gelu_exact(float x) {
    return 0.5f * x * (1.0f + erff(x * 0.7071067811865476f));
}

// dummy kernel purely to align ncu's fixed launch-skip (-s 5) onto a GEMM launch
__global__ void dummy_mark_kernel() {}

// ---------------- TF32 mma.sync GEMM: C[M,N] = A[M,K] @ W[K,N] + bias ----------------
// A: row-major, pre-rounded to tf32. Bp: frag-major permuted weights.
// Block 128x256, 8 warps, warp tile 64x64.
template<bool GELU, bool ROUND>
__global__ __launch_bounds__(256, 1) void gemm_mma(const float* __restrict__ A,
                                                   const float* __restrict__ Bp,
                                                   const float* __restrict__ bias,
                                                   float* __restrict__ C) {
    extern __shared__ float sm[];
    const uint32_t sb0 = smem_u32(sm);
    const int tid = threadIdx.x;
    const int wid = tid >> 5, lane = tid & 31;
    const int g = lane >> 2, tg = lane & 3;
    const int wm = wid >> 2, wn = wid & 3;

    const int n0 = blockIdx.x * BN;
    const int m0 = blockIdx.y * BM;

    const float* Arow = A + (size_t)m0 * KD;
    const float* Bbase = Bp + ((size_t)(n0 >> 4) * 256) * 128;   // pair stride 256 kblks * 128 floats

    float acc[4][8][4];
    #pragma unroll
    for (int mi = 0; mi < 4; mi++)
        #pragma unroll
        for (int ni = 0; ni < 8; ni++)
            #pragma unroll
            for (int r = 0; r < 4; r++) acc[mi][ni][r] = 0.f;

    auto load_stage = [&](int st, int kt) {
        const uint32_t sa = sb0 + st * (STG_F * 4);
        const uint32_t sbB = sa + ASTG_F * 4;
        const int k0 = kt * SKF;
        #pragma unroll
        for (int i = 0; i < 4; i++) {            // A: 1024 x 16B
            const int c = tid + i * 256;
            const int r = c >> 3, cc = c & 7;
            cp_async16(sa + (r * LDK + cc * 4) * 4, Arow + (size_t)r * KD + k0 + cc * 4);
        }
        const int qb = kt * 4;
        #pragma unroll
        for (int i = 0; i < 8; i++) {            // B: 2048 x 16B
            const int c = tid + i * 256;
            const int ll = c & 31, qq = (c >> 5) & 3, pp = c >> 7;
            cp_async16(sbB + (((pp * 4 + qq) * 32 + ll) * 4) * 4,
                       Bbase + ((size_t)pp * 256 + qb + qq) * 128 + ll * 4);
        }
        CP_COMMIT();
    };

    load_stage(0, 0);
    load_stage(1, 1);
    load_stage(2, 2);

    int st = 0;
    for (int kt = 0; kt < KT_STEPS; kt++) {
        CP_WAIT2();
        __syncthreads();
        if (kt + 3 < KT_STEPS) load_stage((st + 3) & (NSTG - 1), kt + 3);
        else CP_COMMIT();   // keep group count uniform for CP_WAIT2

        const float* sa = sm + st * STG_F;
        const float* sbB = sa + ASTG_F;
        #pragma unroll
        for (int ks = 0; ks < 4; ks++) {
            unsigned af[4][4];
            #pragma unroll
            for (int mi = 0; mi < 4; mi++) {
                const float* ap = sa + (wm * 64 + mi * 16) * LDK + ks * 8;
                af[mi][0] = __float_as_uint(ap[(g    ) * LDK + tg    ]);
                af[mi][1] = __float_as_uint(ap[(g + 8) * LDK + tg    ]);
                af[mi][2] = __float_as_uint(ap[(g    ) * LDK + tg + 4]);
                af[mi][3] = __float_as_uint(ap[(g + 8) * LDK + tg + 4]);
            }
            unsigned bf[4][4];
            #pragma unroll
            for (int pp = 0; pp < 4; pp++) {
                const float4 v = *reinterpret_cast<const float4*>(
                    sbB + (((wn * 4 + pp) * 4 + ks) * 32 + lane) * 4);
                bf[pp][0] = __float_as_uint(v.x); bf[pp][1] = __float_as_uint(v.y);
                bf[pp][2] = __float_as_uint(v.z); bf[pp][3] = __float_as_uint(v.w);
            }
            #pragma unroll
            for (int mi = 0; mi < 4; mi++)
                #pragma unroll
                for (int pp = 0; pp < 4; pp++) {
                    mma_tf32(acc[mi][2 * pp    ], af[mi], &bf[pp][0]);
                    mma_tf32(acc[mi][2 * pp + 1], af[mi], &bf[pp][2]);
                }
        }
        st = (st + 1) & (NSTG - 1);
    }

    // epilogue straight from registers
    #pragma unroll
    for (int mi = 0; mi < 4; mi++) {
        #pragma unroll
        for (int ni = 0; ni < 8; ni++) {
            const int r0 = m0 + wm * 64 + mi * 16 + g;
            const int c0 = n0 + wn * 64 + ni * 8 + tg * 2;
            const float b0 = bias[c0], b1v = bias[c0 + 1];
            float v0 = acc[mi][ni][0] + b0;
            float v1 = acc[mi][ni][1] + b1v;
            float v2 = acc[mi][ni][2] + b0;
            float v3 = acc[mi][ni][3] + b1v;
            if (GELU) { v0 = gelu_exact(v0); v1 = gelu_exact(v1); v2 = gelu_exact(v2); v3 = gelu_exact(v3); }
            if (ROUND) { v0 = rna(v0); v1 = rna(v1); v2 = rna(v2); v3 = rna(v3); }
            *reinterpret_cast<float2*>(&C[(size_t)r0 * ND + c0])       = make_float2(v0, v1);
            *reinterpret_cast<float2*>(&C[(size_t)(r0 + 8) * ND + c0]) = make_float2(v2, v3);
        }
    }
}

// ---------------- fused weight permute (all 5 weights): W[K,N] -> frag-major Bp ----------------
// Bp layout: [pair p=n/16][kblk q=k/8][lane][4]:
//   slot0 = W[q*8+tg][p*16+g], slot1 = W[q*8+tg+4][p*16+g],
//   slot2 = W[q*8+tg][p*16+8+g], slot3 = W[q*8+tg+4][p*16+8+g]  (all rna-rounded)
__global__ __launch_bounds__(256) void permute_w5(const float* __restrict__ W0,
                                                  const float* __restrict__ W1,
                                                  const float* __restrict__ W2,
                                                  const float* __restrict__ W3,
                                                  const float* __restrict__ W4,
                                                  float* __restrict__ BpAll) {
    __shared__ float smw[128][17];
    const int tid = threadIdx.x;
    const int p = blockIdx.x;          // 0..127
    const int kc = blockIdx.y;         // 0..15 (128 k each)
    const int widx = blockIdx.z;       // 0..4
    const float* W = (widx == 0) ? W0 : (widx == 1) ? W1 : (widx == 2) ? W2 : (widx == 3) ? W3 : W4;
    float* Bp = BpAll + (size_t)widx * KD * ND;
    const int k0 = kc * 128;
    for (int i = tid; i < 128 * 16; i += 256) {
        const int r = i >> 4, c = i & 15;
        smw[r][c] = W[(size_t)(k0 + r) * ND + p * 16 + c];
    }
    __syncthreads();
    for (int j = tid; j < 16 * 32; j += 256) {
        const int q = j >> 5, l = j & 31, gg = l >> 2, tt = l & 3;
        float4 v;
        v.x = rna(smw[q * 8 + tt    ][gg]);
        v.y = rna(smw[q * 8 + tt + 4][gg]);
        v.z = rna(smw[q * 8 + tt    ][8 + gg]);
        v.w = rna(smw[q * 8 + tt + 4][8 + gg]);
        reinterpret_cast<float4*>(Bp)[((size_t)p * 256 + kc * 16 + q) * 32 + l] = v;
    }
}

// ---------------- elementwise tf32 round ----------------
__global__ __launch_bounds__(256) void round_tf32_kernel(const float* __restrict__ in,
                                                         float* __restrict__ out) {
    const size_t i = ((size_t)blockIdx.x * 256 + threadIdx.x);
    float4 v = reinterpret_cast<const float4*>(in)[i];
    v.x = rna(v.x); v.y = rna(v.y); v.z = rna(v.z); v.w = rna(v.w);
    reinterpret_cast<float4*>(out)[i] = v;
}

// ---------------- fused per-token attention + residual + LN1 ----------------
__global__ __launch_bounds__(256) void attn_ln1_kernel(const float* __restrict__ X,
                                                       const float* __restrict__ g1,
                                                       const float* __restrict__ be1,
                                                       float* __restrict__ X1,
                                                       float* __restrict__ X1r) {
    __shared__ float4 qs4[16 * 32];
    __shared__ float4 ks4[16 * 33];
    __shared__ float4 vs4[16 * 32];
    __shared__ float att[256];
    __shared__ float4 ybuf4[512];
    __shared__ float red[16];

    const int tok = blockIdx.x;
    const int tid = threadIdx.x;
    const size_t base = (size_t)tok * 2048;
    const size_t base4 = base >> 2;

    const float4* Q4 = reinterpret_cast<const float4*>(g_Q);
    const float4* K4 = reinterpret_cast<const float4*>(g_K);
    const float4* V4 = reinterpret_cast<const float4*>(g_V);

    for (int i = tid; i < 512; i += 256) {
        const int h = i >> 5, dd = i & 31;
        qs4[i] = Q4[base4 + i];
        ks4[h * 33 + dd] = K4[base4 + i];
        vs4[i] = V4[base4 + i];
    }
    __syncthreads();

    // scores (h,t)
    {
        const int h = tid >> 4, t = tid & 15;
        float s = 0.f;
        #pragma unroll
        for (int dd = 0; dd < 32; dd++) {
            const float4 q = qs4[h * 32 + dd];
            const float4 k = ks4[t * 33 + dd];
            s += q.x * k.x + q.y * k.y + q.z * k.z + q.w * k.w;
        }
        s *= 0.08838834764831845f;
        float mx = s;
        #pragma unroll
        for (int o = 8; o > 0; o >>= 1) mx = fmaxf(mx, __shfl_xor_sync(0xffffffffu, mx, o, 16));
        const float e = __expf(s - mx);
        float sum = e;
        #pragma unroll
        for (int o = 8; o > 0; o >>= 1) sum += __shfl_xor_sync(0xffffffffu, sum, o, 16);
        att[(tid >> 4) * 16 + t] = e / sum;
    }
    __syncthreads();

    // y = att @ v   (att hoisted to regs, float4 on v)
    {
        const int h2 = tid >> 4, dg = tid & 15;
        float a[16];
        #pragma unroll
        for (int tt = 0; tt < 16; tt++) a[tt] = att[h2 * 16 + tt];
        float4 y0 = make_float4(0.f, 0.f, 0.f, 0.f);
        float4 y1 = make_float4(0.f, 0.f, 0.f, 0.f);
        #pragma unroll
        for (int tt = 0; tt < 16; tt++) {
            const float4 v0 = vs4[tt * 32 + dg];
            const float4 v1 = vs4[tt * 32 + 16 + dg];
            y0.x += a[tt] * v0.x; y0.y += a[tt] * v0.y; y0.z += a[tt] * v0.z; y0.w += a[tt] * v0.w;
            y1.x += a[tt] * v1.x; y1.y += a[tt] * v1.y; y1.z += a[tt] * v1.z; y1.w += a[tt] * v1.w;
        }
        ybuf4[h2 * 32 + dg] = y0;
        ybuf4[h2 * 32 + 16 + dg] = y1;
    }
    __syncthreads();

    // residual + LN1
    const float4* X4 = reinterpret_cast<const float4*>(X);
    float4 z[2];
    float s1 = 0.f, s2 = 0.f;
    #pragma unroll
    for (int j = 0; j < 2; j++) {
        const int i = tid + j * 256;
        const float4 xv = X4[base4 + i];
        const float4 yv = ybuf4[i];
        z[j].x = xv.x + yv.x; z[j].y = xv.y + yv.y; z[j].z = xv.z + yv.z; z[j].w = xv.w + yv.w;
        s1 += z[j].x + z[j].y + z[j].z + z[j].w;
        s2 += z[j].x * z[j].x + z[j].y * z[j].y + z[j].z * z[j].z + z[j].w * z[j].w;
    }
    #pragma unroll
    for (int o = 16; o > 0; o >>= 1) {
        s1 += __shfl_xor_sync(0xffffffffu, s1, o);
        s2 += __shfl_xor_sync(0xffffffffu, s2, o);
    }
    if ((tid & 31) == 0) { red[(tid >> 5) * 2] = s1; red[(tid >> 5) * 2 + 1] = s2; }
    __syncthreads();
    float t1 = 0.f, t2 = 0.f;
    #pragma unroll
    for (int w = 0; w < 8; w++) { t1 += red[w * 2]; t2 += red[w * 2 + 1]; }
    const float mean = t1 * (1.f / 2048.f);
    const float var  = t2 * (1.f / 2048.f) - mean * mean;
    const float inv  = rsqrtf(var + 1e-5f);

    const float4* G4 = reinterpret_cast<const float4*>(g1);
    const float4* B4 = reinterpret_cast<const float4*>(be1);
    float4* X1o  = reinterpret_cast<float4*>(X1);
    float4* X1ro = reinterpret_cast<float4*>(X1r);
    #pragma unroll
    for (int j = 0; j < 2; j++) {
        const int i = tid + j * 256;
        const float4 gv = G4[i], bv = B4[i];
        float4 o, orr;
        o.x = (z[j].x - mean) * inv * gv.x + bv.x;
        o.y = (z[j].y - mean) * inv * gv.y + bv.y;
        o.z = (z[j].z - mean) * inv * gv.z + bv.z;
        o.w = (z[j].w - mean) * inv * gv.w + bv.w;
        orr.x = rna(o.x); orr.y = rna(o.y); orr.z = rna(o.z); orr.w = rna(o.w);
        X1o[base4 + i] = o;
        X1ro[base4 + i] = orr;
    }
}

// ---------------- add + LayerNorm (final) ----------------
__global__ __launch_bounds__(256) void add_ln_kernel(const float* __restrict__ A,
                                                     const float* __restrict__ Bv,
                                                     const float* __restrict__ g,
                                                     const float* __restrict__ be,
                                                     float* __restrict__ out) {
    __shared__ float red[16];
    const int row = blockIdx.x;
    const int tid = threadIdx.x;
    const size_t base4 = ((size_t)row * 2048) >> 2;

    const float4* A4 = reinterpret_cast<const float4*>(A);
    const float4* B4 = reinterpret_cast<const float4*>(Bv);
    float4 z[2];
    float s1 = 0.f, s2 = 0.f;
    #pragma unroll
    for (int j = 0; j < 2; j++) {
        const int i = tid + j * 256;
        const float4 av = A4[base4 + i];
        const float4 bv = B4[base4 + i];
        z[j].x = av.x + bv.x; z[j].y = av.y + bv.y; z[j].z = av.z + bv.z; z[j].w = av.w + bv.w;
        s1 += z[j].x + z[j].y + z[j].z + z[j].w;
        s2 += z[j].x * z[j].x + z[j].y * z[j].y + z[j].z * z[j].z + z[j].w * z[j].w;
    }
    #pragma unroll
    for (int o = 16; o > 0; o >>= 1) {
        s1 += __shfl_xor_sync(0xffffffffu, s1, o);
        s2 += __shfl_xor_sync(0xffffffffu, s2, o);
    }
    if ((tid & 31) == 0) { red[(tid >> 5) * 2] = s1; red[(tid >> 5) * 2 + 1] = s2; }
    __syncthreads();
    float t1 = 0.f, t2 = 0.f;
    #pragma unroll
    for (int w = 0; w < 8; w++) { t1 += red[w * 2]; t2 += red[w * 2 + 1]; }
    const float mean = t1 * (1.f / 2048.f);
    const float var  = t2 * (1.f / 2048.f) - mean * mean;
    const float inv  = rsqrtf(var + 1e-5f);

    const float4* G4 = reinterpret_cast<const float4*>(g);
    const float4* Be4 = reinterpret_cast<const float4*>(be);
    float4* O4 = reinterpret_cast<float4*>(out);
    #pragma unroll
    for (int j = 0; j < 2; j++) {
        const int i = tid + j * 256;
        const float4 gv = G4[i], bv = Be4[i];
        float4 o;
        o.x = (z[j].x - mean) * inv * gv.x + bv.x;
        o.y = (z[j].y - mean) * inv * gv.y + bv.y;
        o.z = (z[j].z - mean) * inv * gv.z + bv.z;
        o.w = (z[j].w - mean) * inv * gv.w + bv.w;
        O4[base4 + i] = o;
    }
}

// ---------------- launch ----------------
extern "C" void kernel_launch(void* const* d_in, const int* in_sizes, int n_in,
                              void* d_out, int out_size) {
    const float* X   = (const float*)d_in[0];
    const float* Wq  = (const float*)d_in[1];
    const float* bq  = (const float*)d_in[2];
    const float* Wk  = (const float*)d_in[3];
    const float* bk  = (const float*)d_in[4];
    const float* Wv  = (const float*)d_in[5];
    const float* bv  = (const float*)d_in[6];
    const float* g1  = (const float*)d_in[7];
    const float* be1 = (const float*)d_in[8];
    const float* W1  = (const float*)d_in[9];
    const float* b1  = (const float*)d_in[10];
    const float* W2  = (const float*)d_in[11];
    const float* b2  = (const float*)d_in[12];
    const float* g2  = (const float*)d_in[13];
    const float* be2 = (const float*)d_in[14];
    float* out = (float*)d_out;

    float *Q, *K, *V, *X1, *X1r, *Hb, *Y2, *Xr, *Wp;
    cudaGetSymbolAddress((void**)&Q,   g_Q);
    cudaGetSymbolAddress((void**)&K,   g_K);
    cudaGetSymbolAddress((void**)&V,   g_V);
    cudaGetSymbolAddress((void**)&X1,  g_X1);
    cudaGetSymbolAddress((void**)&X1r, g_X1r);
    cudaGetSymbolAddress((void**)&Hb,  g_Hb);
    cudaGetSymbolAddress((void**)&Y2,  g_Y2);
    cudaGetSymbolAddress((void**)&Xr,  g_Xr);
    cudaGetSymbolAddress((void**)&Wp,  g_Wp);

    cudaFuncSetAttribute(gemm_mma<false,false>, cudaFuncAttributeMaxDynamicSharedMemorySize, GEMM_SMEM);
    cudaFuncSetAttribute(gemm_mma<true,true>,   cudaFuncAttributeMaxDynamicSharedMemorySize, GEMM_SMEM);

    // launch 0: pre-round X
    round_tf32_kernel<<<(MTOT * (size_t)DDIM) / (256 * 4), 256>>>(X, Xr);
    // launch 1: fused permute of all 5 weights
    dim3 pg(ND / 16, KD / 128, 5);   // (128, 16, 5)
    permute_w5<<<pg, 256>>>(Wq, Wk, Wv, W1, W2, Wp);
    // launch 2: dummy marker so ncu's -s 5 lands on gemm V below
    dummy_mark_kernel<<<1, 1>>>();

    dim3 gg(ND / BN, MTOT / BM);  // (8, 128)
    gemm_mma<false,false><<<gg, 256, GEMM_SMEM>>>(Xr, Wp + 0 * (size_t)KD * ND, bq, Q);  // launch 3
    gemm_mma<false,false><<<gg, 256, GEMM_SMEM>>>(Xr, Wp + 1 * (size_t)KD * ND, bk, K);  // launch 4
    gemm_mma<false,false><<<gg, 256, GEMM_SMEM>>>(Xr, Wp + 2 * (size_t)KD * ND, bv, V);  // launch 5 (profiled)

    attn_ln1_kernel<<<MTOT, 256>>>(X, g1, be1, X1, X1r);

    gemm_mma<true,true>  <<<gg, 256, GEMM_SMEM>>>(X1r, Wp + 3 * (size_t)KD * ND, b1, Hb);
    gemm_mma<false,false><<<gg, 256, GEMM_SMEM>>>(Hb,  Wp + 4 * (size_t)KD * ND, b2, Y2);

    add_ln_kernel<<<MTOT, 256>>>(X1, Y2, g2, be2, out);
}